// round 15
// baseline (speedup 1.0000x reference)
#include <cuda_runtime.h>
#include <cuda_fp16.h>
#include <math.h>

#define MT 8192   // B*T rows
#define DD 1024   // in_features
#define NB 8192   // n_bank
#define DO 1024   // out_features

// ---------------- static device scratch (no allocations allowed) -----------
// NOTE: referenced ONLY from device code (host shadow-address trap).
__device__ __align__(128) __half g_Qh[MT * DD];
__device__ __align__(128) __half g_Kh[NB * DD];
__device__ __align__(128) __half g_Vt[DO * NB];         // V^T [DO][NB] fp16
__device__ __align__(128) __half g_Sh[(size_t)MT * NB]; // fp16 scores
__device__ __align__(128) __half g_G[(size_t)MT * NB];  // gated fp16
__device__ float g_sumsq[MT];
__device__ float g_scale[MT];

// ---------------- helpers ---------------------------------------------------
__device__ __forceinline__ unsigned smem_u32(const void* p) {
    unsigned a;
    asm("{ .reg .u64 t; cvta.to.shared.u64 t, %1; cvt.u32.u64 %0, t; }"
        : "=r"(a) : "l"(p));
    return a;
}
#define CPA16(d, s) \
    asm volatile("cp.async.cg.shared.global [%0], [%1], 16;" :: "r"(d), "l"(s) : "memory")
#define CPCOMMIT() asm volatile("cp.async.commit_group;" ::: "memory")
#define CPWAIT1()  asm volatile("cp.async.wait_group 1;" ::: "memory")

#define LDSM4(r0, r1, r2, r3, a) \
    asm volatile("ldmatrix.sync.aligned.m8n8.x4.shared.b16 {%0,%1,%2,%3}, [%4];" \
        : "=r"(r0), "=r"(r1), "=r"(r2), "=r"(r3) : "r"(a))
#define MMA(c, a, b) \
    asm volatile("mma.sync.aligned.m16n8k16.row.col.f32.f16.f16.f32 " \
        "{%0,%1,%2,%3},{%4,%5,%6,%7},{%8,%9},{%0,%1,%2,%3};" \
        : "+f"((c)[0]), "+f"((c)[1]), "+f"((c)[2]), "+f"((c)[3]) \
        : "r"((a)[0]), "r"((a)[1]), "r"((a)[2]), "r"((a)[3]), \
          "r"((b)[0]), "r"((b)[1]))

// smem tiles: A 64 rows x 32 cols fp16, B 128 rows x 32 cols fp16.
// 64B rows = 4 x 16B segments, swizzled: x = seg ^ ((row>>1)&3).
// Any ldmatrix 8-lane phase group hits 8 distinct 16B offsets mod 128.
#define TILE_A_B 4096               // 64*64
#define TILE_BB  8192               // 128*64
#define STAGE_B  12288              // A + B
// static shared per block: 2 * 12288 = 24576 bytes -> 4 CTAs/SM = 96KB

__device__ __forceinline__ unsigned sw_off(int row, int seg) {
    return (unsigned)(row * 64 + ((seg ^ ((row >> 1) & 3)) << 4));
}

// A tile: 64 rows x 4 segs = 256 x 16B; 128 threads -> 2 each
__device__ __forceinline__ void load_tileA(unsigned sm, const __half* g, int ld,
                                           int k0, int tid) {
#pragma unroll
    for (int j = 0; j < 2; ++j) {
        int i = tid + j * 128;
        int row = i >> 2, seg = i & 3;
        CPA16(sm + sw_off(row, seg), g + (size_t)row * ld + k0 + seg * 8);
    }
}
// B tile: 128 rows x 4 segs = 512 x 16B; 128 threads -> 4 each
__device__ __forceinline__ void load_tileB(unsigned sm, const __half* g, int ld,
                                           int k0, int tid) {
#pragma unroll
    for (int j = 0; j < 4; ++j) {
        int i = tid + j * 128;
        int row = i >> 2, seg = i & 3;
        CPA16(sm + sw_off(row, seg), g + (size_t)row * ld + k0 + seg * 8);
    }
}

// ---------------------------------------------------------------------------
// Single-term fp16 GEMM: D = A * B^T (fp16 in, fp32 accumulate)
// CTA 64x128, K-chunk 32, 2-stage cp.async double buffer, 4 warps (1m x 4n),
// 4 CTAs/SM (cross-CTA latency hiding). Warp tile 64x32, same fragment code
// as the proven 128x128 kernel with wm=0.
// EPI1: write fp16 g_Sh + row sumsq atomics. else: split-K, atomicAdd to Out.
// ---------------------------------------------------------------------------
template<int NC, int LDA, int LDB, bool EPI1>
__global__ __launch_bounds__(128, 4) void gemm_kernel(float* __restrict__ Out,
                                                      int ldo) {
    const __half* __restrict__ A = EPI1 ? g_Qh : g_G;
    const __half* __restrict__ B = EPI1 ? g_Kh : g_Vt;

    __shared__ __align__(128) char dsm[2 * STAGE_B];   // 24576 bytes
    const unsigned sbase = smem_u32(dsm);
    const int tid = threadIdx.x, lane = tid & 31, wn = tid >> 5;
    const int m0 = blockIdx.y * 64, n0 = blockIdx.x * 128;
    const int kbase = EPI1 ? 0 : (int)blockIdx.z * NC * 32;   // split-K offset

    const __half* pA = A + (size_t)m0 * LDA + kbase;
    const __half* pB = B + (size_t)n0 * LDB + kbase;

    float acc[4][4][4];
#pragma unroll
    for (int f = 0; f < 4; ++f)
#pragma unroll
        for (int g = 0; g < 4; ++g)
#pragma unroll
            for (int j = 0; j < 4; ++j) acc[f][g][j] = 0.f;

    // prologue: stages 0,1 <- chunks 0,1
#pragma unroll
    for (int s = 0; s < 2; ++s) {
        unsigned sb = sbase + s * STAGE_B;
        int k0 = s * 32;
        load_tileA(sb,            pA, LDA, k0, tid);
        load_tileB(sb + TILE_A_B, pB, LDB, k0, tid);
        CPCOMMIT();
    }

    // ldmatrix lane addressing
    const int ra = lane & 15, sa = lane >> 4;            // A x4: row, seg-half
    const int rbp = (lane & 7) + ((lane >> 4) << 3);     // B paired x4
    const int sbp = (lane >> 3) & 1;

    for (int c = 0; c < NC; ++c) {
        CPWAIT1();
        __syncthreads();
        unsigned sb = sbase + (c & 1) * STAGE_B;
#pragma unroll
        for (int h = 0; h < 2; ++h) {                    // two k16 steps
            unsigned a[4][4], b[4][2];
#pragma unroll
            for (int f = 0; f < 4; ++f) {
                unsigned ad = sb + sw_off(f * 16 + ra, h * 2 + sa);
                LDSM4(a[f][0], a[f][1], a[f][2], a[f][3], ad);
            }
#pragma unroll
            for (int p = 0; p < 2; ++p) {                // g-pair {2p, 2p+1}
                unsigned bd = sb + TILE_A_B +
                              sw_off(wn * 32 + p * 16 + rbp, h * 2 + sbp);
                LDSM4(b[2 * p][0], b[2 * p][1],
                      b[2 * p + 1][0], b[2 * p + 1][1], bd);
            }
#pragma unroll
            for (int f = 0; f < 4; ++f)
#pragma unroll
                for (int g = 0; g < 4; ++g)
                    MMA(acc[f][g], a[f], b[g]);
        }
        __syncthreads();
        if (c + 2 < NC) {
            unsigned sn = sbase + (c & 1) * STAGE_B;
            int k0 = (c + 2) * 32;
            load_tileA(sn,            pA, LDA, k0, tid);
            load_tileB(sn + TILE_A_B, pB, LDB, k0, tid);
        }
        CPCOMMIT();
    }

    // epilogue
    const int mrb = m0 + (lane >> 2);
    const int ncb = n0 + wn * 32 + (lane & 3) * 2;
#pragma unroll
    for (int f = 0; f < 4; ++f) {
        const int r0 = mrb + f * 16;
        float s0 = 0.f, s1 = 0.f;
#pragma unroll
        for (int g = 0; g < 4; ++g) {
            const int cc = ncb + g * 8;
            if (EPI1) {
                *(__half2*)&g_Sh[(size_t)r0 * NB + cc] =
                    __floats2half2_rn(acc[f][g][0], acc[f][g][1]);
                *(__half2*)&g_Sh[(size_t)(r0 + 8) * NB + cc] =
                    __floats2half2_rn(acc[f][g][2], acc[f][g][3]);
                s0 += acc[f][g][0] * acc[f][g][0] + acc[f][g][1] * acc[f][g][1];
                s1 += acc[f][g][2] * acc[f][g][2] + acc[f][g][3] * acc[f][g][3];
            } else {
                float* p0 = &Out[(size_t)r0 * ldo + cc];
                float* p1 = &Out[(size_t)(r0 + 8) * ldo + cc];
                atomicAdd(p0,     acc[f][g][0]);
                atomicAdd(p0 + 1, acc[f][g][1]);
                atomicAdd(p1,     acc[f][g][2]);
                atomicAdd(p1 + 1, acc[f][g][3]);
            }
        }
        if (EPI1) {
            s0 += __shfl_xor_sync(0xffffffff, s0, 1);
            s0 += __shfl_xor_sync(0xffffffff, s0, 2);
            s1 += __shfl_xor_sync(0xffffffff, s1, 1);
            s1 += __shfl_xor_sync(0xffffffff, s1, 2);
            if ((lane & 3) == 0) {
                atomicAdd(&g_sumsq[r0], s0);
                atomicAdd(&g_sumsq[r0 + 8], s1);
            }
        }
    }
}

// ---------------- elementwise kernels --------------------------------------
__global__ __launch_bounds__(256) void convQK_kernel(const float* __restrict__ q,
                                                     const float* __restrict__ k) {
    size_t i = (size_t)blockIdx.x * 256 + threadIdx.x;    // over MT*DD/4
    float4 vq = ((const float4*)q)[i];
    float4 vk = ((const float4*)k)[i];
    union { __half h[4]; uint2 u; } H;
    H.h[0] = __float2half_rn(vq.x); H.h[1] = __float2half_rn(vq.y);
    H.h[2] = __float2half_rn(vq.z); H.h[3] = __float2half_rn(vq.w);
    ((uint2*)g_Qh)[i] = H.u;
    H.h[0] = __float2half_rn(vk.x); H.h[1] = __float2half_rn(vk.y);
    H.h[2] = __float2half_rn(vk.z); H.h[3] = __float2half_rn(vk.w);
    ((uint2*)g_Kh)[i] = H.u;
}

__global__ void vtrans_kernel(const float* __restrict__ V) {
    __shared__ float t[32][33];
    const int o0 = blockIdx.x * 32, n0 = blockIdx.y * 32;
    const int tx = threadIdx.x, ty = threadIdx.y;
    for (int r = ty; r < 32; r += 8)
        t[r][tx] = V[(size_t)(n0 + r) * DO + o0 + tx];
    __syncthreads();
    for (int r = ty; r < 32; r += 8)
        g_Vt[(size_t)(o0 + r) * NB + n0 + tx] = __float2half_rn(t[tx][r]);
}

__global__ void zero_sumsq_kernel() {
    int i = blockIdx.x * 256 + threadIdx.x;
    if (i < MT) g_sumsq[i] = 0.f;
}
__global__ void row_scale_kernel2() {
    int i = blockIdx.x * 256 + threadIdx.x;
    if (i < MT) g_scale[i] = 90.50966799187809f / sqrtf(g_sumsq[i]);
}

__global__ __launch_bounds__(256) void zero_out_kernel(float* __restrict__ O) {
    size_t i = (size_t)blockIdx.x * 256 + threadIdx.x;    // over MT*DO/4
    ((float4*)O)[i] = make_float4(0.f, 0.f, 0.f, 0.f);
}

__global__ __launch_bounds__(256) void gating_kernel() {
    size_t i = (size_t)blockIdx.x * 256 + threadIdx.x;    // over MT*NB/8
    size_t off = i * 8;
    const float sc = g_scale[off >> 13];
    union { __half h[8]; uint4 v; } IN, OH;
    IN.v = *(const uint4*)(g_Sh + off);
#pragma unroll
    for (int j = 0; j < 8; ++j) {
        float x = __half2float(IN.h[j]) * sc;
        OH.h[j] = __float2half_rn(0.5f * x * (1.0f + erff(x * 0.70710678118654752f)));
    }
    *(uint4*)(g_G + off) = OH.v;
}

// ---------------------------------------------------------------------------
extern "C" void kernel_launch(void* const* d_in, const int* in_sizes, int n_in,
                              void* d_out, int out_size) {
    const float* q = (const float*)d_in[0];
    const float* k = (const float*)d_in[1];
    const float* v = (const float*)d_in[2];
    float* o = (float*)d_out;

    convQK_kernel<<<(MT * DD / 4) / 256, 256>>>(q, k);
    vtrans_kernel<<<dim3(DO / 32, NB / 32), dim3(32, 8)>>>(v);
    zero_sumsq_kernel<<<MT / 256, 256>>>();
    gemm_kernel<DD / 32, DD, DD, true><<<dim3(NB / 128, MT / 64), 128>>>(
        nullptr, NB);
    row_scale_kernel2<<<MT / 256, 256>>>();
    gating_kernel<<<(int)((size_t)MT * NB / 8 / 256), 256>>>();
    zero_out_kernel<<<(MT * DO / 4) / 256, 256>>>(o);
    // split-K=4: each z-slice sums a quarter of K into o via atomicAdd
    gemm_kernel<NB / 128, NB, NB, false><<<dim3(DO / 128, MT / 64, 4), 128>>>(
        o, DO);
}